// round 15
// baseline (speedup 1.0000x reference)
#include <cuda_runtime.h>
#include <cstdint>

typedef unsigned long long ull;

#define SEQ    96
#define NHEAD  8
#define DHEAD  32
#define DMOD   256
#define NBATCH 1024
#define MTOT   (NBATCH*SEQ)   // 98304
#define NDIAG  33

// ---------------- scratch (static device globals) ----------------
__device__ float g_q[NBATCH*NHEAD*SEQ*DHEAD];
__device__ float g_k[NBATCH*NHEAD*SEQ*DHEAD];
__device__ float g_v[NBATCH*NHEAD*SEQ*DHEAD];
__device__ float g_ao[MTOT*DMOD];

// ---------------- helpers ----------------
__device__ __forceinline__ ull pack2(float x, float y) {
    ull r; asm("mov.b64 %0, {%1,%2};" : "=l"(r) : "f"(x), "f"(y)); return r;
}
__device__ __forceinline__ void ffma2(ull &d, ull a, ull b) {
    asm("fma.rn.f32x2 %0, %1, %2, %0;" : "+l"(d) : "l"(a), "l"(b));
}
__device__ __forceinline__ float2 unpack2(ull v) {
    float2 f; asm("mov.b64 {%0,%1}, %2;" : "=f"(f.x), "=f"(f.y) : "l"(v)); return f;
}
__device__ __forceinline__ uint32_t smem_u32(const void* p){
    uint32_t a;
    asm("{ .reg .u64 t; cvta.to.shared.u64 t, %1; cvt.u32.u64 %0, t; }" : "=r"(a) : "l"(p));
    return a;
}
__device__ __forceinline__ void ldsm4(uint32_t& r0, uint32_t& r1, uint32_t& r2,
                                      uint32_t& r3, uint32_t a){
    asm volatile("ldmatrix.sync.aligned.m8n8.x4.shared.b16 {%0,%1,%2,%3}, [%4];"
        : "=r"(r0), "=r"(r1), "=r"(r2), "=r"(r3) : "r"(a));
}
__device__ __forceinline__ void mma_bf16(float* c, const uint32_t* a,
                                         uint32_t b0, uint32_t b1){
    asm volatile("mma.sync.aligned.m16n8k16.row.col.f32.bf16.bf16.f32 "
        "{%0,%1,%2,%3}, {%4,%5,%6,%7}, {%8,%9}, {%0,%1,%2,%3};"
        : "+f"(c[0]), "+f"(c[1]), "+f"(c[2]), "+f"(c[3])
        : "r"(a[0]), "r"(a[1]), "r"(a[2]), "r"(a[3]), "r"(b0), "r"(b1));
}
__device__ __forceinline__ void bsplit2(float x, float y, uint32_t& h2, uint32_t& l2){
    asm("cvt.rn.bf16x2.f32 %0, %1, %2;" : "=r"(h2) : "f"(y), "f"(x));
    float hx = __uint_as_float(h2 << 16);
    float hy = __uint_as_float(h2 & 0xffff0000u);
    float rx = x - hx;
    float ry = y - hy;
    asm("cvt.rn.bf16x2.f32 %0, %1, %2;" : "=r"(l2) : "f"(ry), "f"(rx));
}
__device__ __forceinline__ void sts128(uint32_t a, uint32_t r0, uint32_t r1,
                                       uint32_t r2, uint32_t r3){
    asm volatile("st.shared.v4.b32 [%0], {%1,%2,%3,%4};"
        :: "r"(a), "r"(r0), "r"(r1), "r"(r2), "r"(r3) : "memory");
}

// SMEM stage layout (bf16 tiles, rows padded to 80B)
#define ROWB  80
#define ST_AH 0
#define ST_AL 10240
#define ST_BH 20480
#define ST_BL 40960
#define STG   61440
#define SMEMB (2*STG)   // 122880

// ---------------- bf16x3 tensor-core GEMM (R11 base + interleaved sts) -----
template<int QKV>
__global__ void __launch_bounds__(256, 1) gemm_mma(
    const float* __restrict__ Ain,
    const float* __restrict__ W0, const float* __restrict__ W1,
    const float* __restrict__ W2,
    float* __restrict__ Cout)
{
    extern __shared__ __align__(128) char smem[];
    const uint32_t sb = smem_u32(smem);
    const int tid  = threadIdx.x;
    const int lane = tid & 31;
    const int wid  = tid >> 5;

    const float* W; float* dst;
    if (QKV) {
        const int z = blockIdx.y;
        W   = (z == 0) ? W0  : (z == 1) ? W1  : W2;
        dst = (z == 0) ? g_q : (z == 1) ? g_k : g_v;
    } else { W = W0; dst = Cout; }
    const float* Ab = QKV ? Ain : (const float*)g_ao;
    const int m0 = blockIdx.x * 128;

    // loader mapping (R11: coalesced-across-lanes)
    const int ar = tid & 127;
    const int ah = (tid >> 7) << 4;
    const float* gA = Ab + (size_t)(m0 + ar) * DMOD + ah;
    const uint32_t aDst = (uint32_t)ar * ROWB + (uint32_t)(ah << 1);
    const float* gB = W + tid;
    const uint32_t bDst = (uint32_t)tid * ROWB;

    // compute mapping: warp tile 64x64
    const int mW = (wid & 1) * 64;
    const int nW = (wid >> 1) * 64;
    const int q  = lane >> 3;
    const int rl = lane & 7;
    const uint32_t aOff = (uint32_t)(mW + (q & 1) * 8 + rl) * ROWB + (uint32_t)((q >> 1) * 16);
    const uint32_t bOff = (uint32_t)(nW + (q >> 1) * 8 + rl) * ROWB + (uint32_t)((q & 1) * 16);

    float acc[4][8][4];
    #pragma unroll
    for (int mi = 0; mi < 4; mi++)
        #pragma unroll
        for (int ni = 0; ni < 8; ni++)
            #pragma unroll
            for (int t = 0; t < 4; t++) acc[mi][ni][t] = 0.f;

    float fa[16], fb[32];

    auto ldgA = [&](int c){
        const float* p = gA + c * 32;
        *(float4*)(fa + 0)  = *(const float4*)(p + 0);
        *(float4*)(fa + 4)  = *(const float4*)(p + 4);
        *(float4*)(fa + 8)  = *(const float4*)(p + 8);
        *(float4*)(fa + 12) = *(const float4*)(p + 12);
    };
    auto ldgB = [&](int c){
        const float* p = gB + (size_t)c * 32 * DMOD;
        #pragma unroll
        for (int i = 0; i < 32; i++) fb[i] = p[(size_t)i * DMOD];
    };
    auto stsA = [&](uint32_t sBase){
        uint32_t h[8], l[8];
        #pragma unroll
        for (int i = 0; i < 8; i++) bsplit2(fa[2*i], fa[2*i+1], h[i], l[i]);
        sts128(sBase + ST_AH + aDst,      h[0], h[1], h[2], h[3]);
        sts128(sBase + ST_AH + aDst + 16, h[4], h[5], h[6], h[7]);
        sts128(sBase + ST_AL + aDst,      l[0], l[1], l[2], l[3]);
        sts128(sBase + ST_AL + aDst + 16, l[4], l[5], l[6], l[7]);
    };
    auto stsB = [&](uint32_t sBase){
        uint32_t h[16], l[16];
        #pragma unroll
        for (int i = 0; i < 16; i++) bsplit2(fb[2*i], fb[2*i+1], h[i], l[i]);
        sts128(sBase + ST_BH + bDst,      h[0],  h[1],  h[2],  h[3]);
        sts128(sBase + ST_BH + bDst + 16, h[4],  h[5],  h[6],  h[7]);
        sts128(sBase + ST_BH + bDst + 32, h[8],  h[9],  h[10], h[11]);
        sts128(sBase + ST_BH + bDst + 48, h[12], h[13], h[14], h[15]);
        sts128(sBase + ST_BL + bDst,      l[0],  l[1],  l[2],  l[3]);
        sts128(sBase + ST_BL + bDst + 16, l[4],  l[5],  l[6],  l[7]);
        sts128(sBase + ST_BL + bDst + 32, l[8],  l[9],  l[10], l[11]);
        sts128(sBase + ST_BL + bDst + 48, l[12], l[13], l[14], l[15]);
    };

    ldgA(0); ldgB(0);
    stsA(sb); stsB(sb);
    ldgA(1); ldgB(1);
    __syncthreads();

    #pragma unroll 1
    for (int c = 0; c < 8; c++){
        const uint32_t sBuf = sb + (uint32_t)(c & 1) * STG;
        const uint32_t sNxt = sb + (uint32_t)((c + 1) & 1) * STG;
        const uint32_t aH = sBuf + ST_AH + aOff;
        const uint32_t aL = sBuf + ST_AL + aOff;
        const uint32_t bH = sBuf + ST_BH + bOff;
        const uint32_t bL = sBuf + ST_BL + bOff;

        // ================= k16 = 0 =================
        {
            const uint32_t ko = 0;
            uint32_t A_[16], A2_[16], B_[16];
            #pragma unroll
            for (int mi = 0; mi < 4; mi++)
                ldsm4(A_[4*mi], A_[4*mi+1], A_[4*mi+2], A_[4*mi+3],
                      aH + ko + (uint32_t)mi * (16*ROWB));
            #pragma unroll
            for (int mi = 0; mi < 4; mi++)
                ldsm4(A2_[4*mi], A2_[4*mi+1], A2_[4*mi+2], A2_[4*mi+3],
                      aL + ko + (uint32_t)mi * (16*ROWB));
            #pragma unroll
            for (int j = 0; j < 4; j++)
                ldsm4(B_[4*j], B_[4*j+1], B_[4*j+2], B_[4*j+3],
                      bH + ko + (uint32_t)j * (16*ROWB));
            // term 1: Ah x Bh
            #pragma unroll
            for (int mi = 0; mi < 4; mi++)
                #pragma unroll
                for (int ni = 0; ni < 8; ni++)
                    mma_bf16(acc[mi][ni], &A_[4*mi], B_[2*ni], B_[2*ni+1]);
            // interleave: store A-planes of chunk c+1 while tensor pipe drains
            if (c < 7) stsA(sNxt);
            // term 3: Al x Bh
            #pragma unroll
            for (int mi = 0; mi < 4; mi++)
                #pragma unroll
                for (int ni = 0; ni < 8; ni++)
                    mma_bf16(acc[mi][ni], &A2_[4*mi], B_[2*ni], B_[2*ni+1]);
            // term 2: Ah x Bl
            #pragma unroll
            for (int j = 0; j < 4; j++)
                ldsm4(B_[4*j], B_[4*j+1], B_[4*j+2], B_[4*j+3],
                      bL + ko + (uint32_t)j * (16*ROWB));
            #pragma unroll
            for (int mi = 0; mi < 4; mi++)
                #pragma unroll
                for (int ni = 0; ni < 8; ni++)
                    mma_bf16(acc[mi][ni], &A_[4*mi], B_[2*ni], B_[2*ni+1]);
        }
        // ================= k16 = 1 =================
        {
            const uint32_t ko = 32;
            uint32_t A_[16], A2_[16], B_[16];
            #pragma unroll
            for (int mi = 0; mi < 4; mi++)
                ldsm4(A_[4*mi], A_[4*mi+1], A_[4*mi+2], A_[4*mi+3],
                      aH + ko + (uint32_t)mi * (16*ROWB));
            #pragma unroll
            for (int mi = 0; mi < 4; mi++)
                ldsm4(A2_[4*mi], A2_[4*mi+1], A2_[4*mi+2], A2_[4*mi+3],
                      aL + ko + (uint32_t)mi * (16*ROWB));
            #pragma unroll
            for (int j = 0; j < 4; j++)
                ldsm4(B_[4*j], B_[4*j+1], B_[4*j+2], B_[4*j+3],
                      bH + ko + (uint32_t)j * (16*ROWB));
            // term 1: Ah x Bh
            #pragma unroll
            for (int mi = 0; mi < 4; mi++)
                #pragma unroll
                for (int ni = 0; ni < 8; ni++)
                    mma_bf16(acc[mi][ni], &A_[4*mi], B_[2*ni], B_[2*ni+1]);
            // interleave: store B-planes of chunk c+1
            if (c < 7) stsB(sNxt);
            // term 3: Al x Bh
            #pragma unroll
            for (int mi = 0; mi < 4; mi++)
                #pragma unroll
                for (int ni = 0; ni < 8; ni++)
                    mma_bf16(acc[mi][ni], &A2_[4*mi], B_[2*ni], B_[2*ni+1]);
            // term 2: Ah x Bl
            #pragma unroll
            for (int j = 0; j < 4; j++)
                ldsm4(B_[4*j], B_[4*j+1], B_[4*j+2], B_[4*j+3],
                      bL + ko + (uint32_t)j * (16*ROWB));
            #pragma unroll
            for (int mi = 0; mi < 4; mi++)
                #pragma unroll
                for (int ni = 0; ni < 8; ni++)
                    mma_bf16(acc[mi][ni], &A_[4*mi], B_[2*ni], B_[2*ni+1]);
        }
        // start LDG of chunk c+2 into fa/fb (consumed by sts next iteration)
        if (c < 6) { ldgA(c + 2); ldgB(c + 2); }
        __syncthreads();
    }

    // epilogue
    const int r0q = lane >> 2;
    const int c0q = (lane & 3) * 2;
    #pragma unroll
    for (int mi = 0; mi < 4; mi++){
        #pragma unroll
        for (int half = 0; half < 2; half++){
            const int row = m0 + mW + mi * 16 + half * 8 + r0q;
            if (QKV){
                const int nb = row / SEQ, l = row % SEQ;
                float* base = dst + (((size_t)nb * NHEAD) * SEQ + l) * DHEAD;
                #pragma unroll
                for (int ni = 0; ni < 8; ni++){
                    const int col = nW + ni * 8 + c0q;
                    const int h = col >> 5, cc = col & 31;
                    float2 v;
                    v.x = acc[mi][ni][half*2+0];
                    v.y = acc[mi][ni][half*2+1];
                    *(float2*)(base + (size_t)h * (SEQ*DHEAD) + cc) = v;
                }
            } else {
                float* base = dst + (size_t)row * DMOD;
                #pragma unroll
                for (int ni = 0; ni < 8; ni++){
                    const int col = nW + ni * 8 + c0q;
                    float2 v;
                    v.x = acc[mi][ni][half*2+0];
                    v.y = acc[mi][ni][half*2+1];
                    *(float2*)(base + col) = v;
                }
            }
        }
    }
}

// ---------------- banded attention (R5-proven): one block per (n,h) --------
__global__ void __launch_bounds__(96) attn_kernel(const float* __restrict__ rel_bias)
{
    const int nh = blockIdx.x;
    const int h  = nh & 7;
    const int n  = nh >> 3;

    __shared__ __align__(16) float ks[SEQ][34];
    __shared__ __align__(16) float vs[SEQ][34];
    __shared__ float sbias[NDIAG];

    const int tid = threadIdx.x;
    const float* kg = g_k + (size_t)nh * (SEQ * DHEAD);
    const float* vg = g_v + (size_t)nh * (SEQ * DHEAD);

    for (int idx = tid; idx < SEQ * DHEAD; idx += 96) {
        const int r = idx >> 5, c = idx & 31;
        ks[r][c] = kg[idx];
        vs[r][c] = vg[idx];
    }
    if (tid < NDIAG) {
        const int dd  = tid - 16;
        const int rel = (96 - dd) % 96;
        sbias[tid] = rel_bias[h * 96 + rel];
    }
    __syncthreads();

    const int i = tid;
    const float* qg = g_q + (size_t)nh * (SEQ * DHEAD) + (size_t)i * DHEAD;
    float qv[32];
    #pragma unroll
    for (int c4 = 0; c4 < 8; c4++) {
        float4 t = *(const float4*)(qg + c4 * 4);
        qv[c4*4+0] = t.x; qv[c4*4+1] = t.y; qv[c4*4+2] = t.z; qv[c4*4+3] = t.w;
    }
    ull qq[16];
    #pragma unroll
    for (int t = 0; t < 16; t++) qq[t] = pack2(qv[2*t], qv[2*t+1]);

    const float scale = 0.17677669529663687f;
    float logit[NDIAG];
    #pragma unroll
    for (int d = 0; d < NDIAG; d++) {
        int j = i + d - 16;
        if (j < 0)   j += 96;
        if (j >= 96) j -= 96;
        const ull* kp = (const ull*)&ks[j][0];
        ull a2 = 0ull;
        #pragma unroll
        for (int t = 0; t < 16; t++) ffma2(a2, qq[t], kp[t]);
        float2 s2 = unpack2(a2);
        logit[d] = (s2.x + s2.y) * scale + sbias[d];
    }

    float mx = logit[0];
    #pragma unroll
    for (int d = 1; d < NDIAG; d++) mx = fmaxf(mx, logit[d]);
    float sum = 0.f;
    #pragma unroll
    for (int d = 0; d < NDIAG; d++) { logit[d] = __expf(logit[d] - mx); sum += logit[d]; }

    ull o2[16];
    #pragma unroll
    for (int t = 0; t < 16; t++) o2[t] = 0ull;
    #pragma unroll
    for (int d = 0; d < NDIAG; d++) {
        int j = i + d - 16;
        if (j < 0)   j += 96;
        if (j >= 96) j -= 96;
        const ull ww = pack2(logit[d], logit[d]);
        const ull* vp = (const ull*)&vs[j][0];
        #pragma unroll
        for (int t = 0; t < 16; t++) ffma2(o2[t], ww, vp[t]);
    }

    const float inv = 1.0f / sum;
    float* og = g_ao + ((size_t)n * SEQ + i) * DMOD + h * DHEAD;
    #pragma unroll
    for (int t = 0; t < 16; t++) {
        float2 v = unpack2(o2[t]);
        float2 r; r.x = v.x * inv; r.y = v.y * inv;
        *(float2*)(og + 2 * t) = r;
    }
}

// ---------------- entry point ----------------
extern "C" void kernel_launch(void* const* d_in, const int* in_sizes, int n_in,
                              void* d_out, int out_size)
{
    (void)in_sizes; (void)n_in; (void)out_size;
    const float* Z  = (const float*)d_in[0];
    const float* Wq = (const float*)d_in[1];
    const float* Wk = (const float*)d_in[2];
    const float* Wv = (const float*)d_in[3];
    const float* Wo = (const float*)d_in[4];
    const float* rb = (const float*)d_in[5];
    float* out = (float*)d_out;

    cudaFuncSetAttribute(gemm_mma<1>, cudaFuncAttributeMaxDynamicSharedMemorySize, SMEMB);
    cudaFuncSetAttribute(gemm_mma<0>, cudaFuncAttributeMaxDynamicSharedMemorySize, SMEMB);

    dim3 g1(MTOT / 128, 3);
    gemm_mma<1><<<g1, 256, SMEMB>>>(Z, Wq, Wk, Wv, nullptr);

    attn_kernel<<<NBATCH * NHEAD, 96>>>(rb);

    dim3 g2(MTOT / 128, 1);
    gemm_mma<0><<<g2, 256, SMEMB>>>(nullptr, Wo, nullptr, nullptr, out);
}

// round 16
// speedup vs baseline: 1.5597x; 1.5597x over previous
#include <cuda_runtime.h>
#include <cstdint>

typedef unsigned long long ull;

#define SEQ    96
#define NHEAD  8
#define DHEAD  32
#define DMOD   256
#define NBATCH 1024
#define MTOT   (NBATCH*SEQ)   // 98304
#define NDIAG  33

// ---------------- scratch (static device globals) ----------------
__device__ float g_q[NBATCH*NHEAD*SEQ*DHEAD];
__device__ float g_k[NBATCH*NHEAD*SEQ*DHEAD];
__device__ float g_v[NBATCH*NHEAD*SEQ*DHEAD];
__device__ float g_ao[MTOT*DMOD];

// ---------------- helpers ----------------
__device__ __forceinline__ ull pack2(float x, float y) {
    ull r; asm("mov.b64 %0, {%1,%2};" : "=l"(r) : "f"(x), "f"(y)); return r;
}
__device__ __forceinline__ void ffma2(ull &d, ull a, ull b) {
    asm("fma.rn.f32x2 %0, %1, %2, %0;" : "+l"(d) : "l"(a), "l"(b));
}
__device__ __forceinline__ float2 unpack2(ull v) {
    float2 f; asm("mov.b64 {%0,%1}, %2;" : "=f"(f.x), "=f"(f.y) : "l"(v)); return f;
}
__device__ __forceinline__ uint32_t smem_u32(const void* p){
    uint32_t a;
    asm("{ .reg .u64 t; cvta.to.shared.u64 t, %1; cvt.u32.u64 %0, t; }" : "=r"(a) : "l"(p));
    return a;
}
__device__ __forceinline__ void ldsm4(uint32_t& r0, uint32_t& r1, uint32_t& r2,
                                      uint32_t& r3, uint32_t a){
    asm volatile("ldmatrix.sync.aligned.m8n8.x4.shared.b16 {%0,%1,%2,%3}, [%4];"
        : "=r"(r0), "=r"(r1), "=r"(r2), "=r"(r3) : "r"(a));
}
__device__ __forceinline__ void mma_bf16(float* c, const uint32_t* a,
                                         uint32_t b0, uint32_t b1){
    asm volatile("mma.sync.aligned.m16n8k16.row.col.f32.bf16.bf16.f32 "
        "{%0,%1,%2,%3}, {%4,%5,%6,%7}, {%8,%9}, {%0,%1,%2,%3};"
        : "+f"(c[0]), "+f"(c[1]), "+f"(c[2]), "+f"(c[3])
        : "r"(a[0]), "r"(a[1]), "r"(a[2]), "r"(a[3]), "r"(b0), "r"(b1));
}
__device__ __forceinline__ void bsplit2(float x, float y, uint32_t& h2, uint32_t& l2){
    asm("cvt.rn.bf16x2.f32 %0, %1, %2;" : "=r"(h2) : "f"(y), "f"(x));
    float hx = __uint_as_float(h2 << 16);
    float hy = __uint_as_float(h2 & 0xffff0000u);
    float rx = x - hx;
    float ry = y - hy;
    asm("cvt.rn.bf16x2.f32 %0, %1, %2;" : "=r"(l2) : "f"(ry), "f"(rx));
}
__device__ __forceinline__ void sts128(uint32_t a, uint32_t r0, uint32_t r1,
                                       uint32_t r2, uint32_t r3){
    asm volatile("st.shared.v4.b32 [%0], {%1,%2,%3,%4};"
        :: "r"(a), "r"(r0), "r"(r1), "r"(r2), "r"(r3) : "memory");
}

// SMEM stage layout (bf16 tiles, rows padded to 80B)
#define ROWB  80
#define ST_AH 0
#define ST_AL 10240
#define ST_BH 20480
#define ST_BL 40960
#define STG   61440
#define SMEMB (2*STG)   // 122880

// ---------------- bf16x3 tensor-core GEMM (R11-banked: 360/118us) ----------
// QKV=1: blockIdx.x selects Wq/Wk/Wv (z fastest -> A tiles shared in L2);
//        blockIdx.y = m-tile. Epilogue scatters to g_q/g_k/g_v.
// QKV=0: W0 = Wo, A = g_ao, writes Cout row-major.
template<int QKV>
__global__ void __launch_bounds__(256, 1) gemm_mma(
    const float* __restrict__ Ain,
    const float* __restrict__ W0, const float* __restrict__ W1,
    const float* __restrict__ W2,
    float* __restrict__ Cout)
{
    extern __shared__ __align__(128) char smem[];
    const uint32_t sb = smem_u32(smem);
    const int tid  = threadIdx.x;
    const int lane = tid & 31;
    const int wid  = tid >> 5;

    const float* W; float* dst;
    if (QKV) {
        const int z = blockIdx.x;
        W   = (z == 0) ? W0  : (z == 1) ? W1  : W2;
        dst = (z == 0) ? g_q : (z == 1) ? g_k : g_v;
    } else { W = W0; dst = Cout; }
    const float* Ab = QKV ? Ain : (const float*)g_ao;
    const int m0 = (QKV ? blockIdx.y : blockIdx.x) * 128;

    // loader mapping (coalesced across lanes)
    const int ar = tid & 127;
    const int ah = (tid >> 7) << 4;
    const float* gA = Ab + (size_t)(m0 + ar) * DMOD + ah;
    const uint32_t aDst = (uint32_t)ar * ROWB + (uint32_t)(ah << 1);
    const float* gB = W + tid;
    const uint32_t bDst = (uint32_t)tid * ROWB;

    // compute mapping: warp tile 64x64
    const int mW = (wid & 1) * 64;
    const int nW = (wid >> 1) * 64;
    const int q  = lane >> 3;
    const int rl = lane & 7;
    const uint32_t aOff = (uint32_t)(mW + (q & 1) * 8 + rl) * ROWB + (uint32_t)((q >> 1) * 16);
    const uint32_t bOff = (uint32_t)(nW + (q >> 1) * 8 + rl) * ROWB + (uint32_t)((q & 1) * 16);

    float acc[4][8][4];
    #pragma unroll
    for (int mi = 0; mi < 4; mi++)
        #pragma unroll
        for (int ni = 0; ni < 8; ni++)
            #pragma unroll
            for (int t = 0; t < 4; t++) acc[mi][ni][t] = 0.f;

    float fa[16], fb[32];

    auto ldgA = [&](int c){
        const float* p = gA + c * 32;
        *(float4*)(fa + 0)  = *(const float4*)(p + 0);
        *(float4*)(fa + 4)  = *(const float4*)(p + 4);
        *(float4*)(fa + 8)  = *(const float4*)(p + 8);
        *(float4*)(fa + 12) = *(const float4*)(p + 12);
    };
    auto ldgB = [&](int c){
        const float* p = gB + (size_t)c * 32 * DMOD;
        #pragma unroll
        for (int i = 0; i < 32; i++) fb[i] = p[(size_t)i * DMOD];
    };
    auto stsAB = [&](uint32_t sBase){
        uint32_t h[16], l[16];
        #pragma unroll
        for (int i = 0; i < 8; i++) bsplit2(fa[2*i], fa[2*i+1], h[i], l[i]);
        sts128(sBase + ST_AH + aDst,      h[0], h[1], h[2], h[3]);
        sts128(sBase + ST_AH + aDst + 16, h[4], h[5], h[6], h[7]);
        sts128(sBase + ST_AL + aDst,      l[0], l[1], l[2], l[3]);
        sts128(sBase + ST_AL + aDst + 16, l[4], l[5], l[6], l[7]);
        #pragma unroll
        for (int i = 0; i < 16; i++) bsplit2(fb[2*i], fb[2*i+1], h[i], l[i]);
        sts128(sBase + ST_BH + bDst,      h[0],  h[1],  h[2],  h[3]);
        sts128(sBase + ST_BH + bDst + 16, h[4],  h[5],  h[6],  h[7]);
        sts128(sBase + ST_BH + bDst + 32, h[8],  h[9],  h[10], h[11]);
        sts128(sBase + ST_BH + bDst + 48, h[12], h[13], h[14], h[15]);
        sts128(sBase + ST_BL + bDst,      l[0],  l[1],  l[2],  l[3]);
        sts128(sBase + ST_BL + bDst + 16, l[4],  l[5],  l[6],  l[7]);
        sts128(sBase + ST_BL + bDst + 32, l[8],  l[9],  l[10], l[11]);
        sts128(sBase + ST_BL + bDst + 48, l[12], l[13], l[14], l[15]);
    };

    ldgA(0); ldgB(0);
    stsAB(sb);
    ldgA(1); ldgB(1);
    __syncthreads();

    #pragma unroll 1
    for (int c = 0; c < 8; c++){
        const uint32_t sBuf = sb + (uint32_t)(c & 1) * STG;
        const uint32_t aH = sBuf + ST_AH + aOff;
        const uint32_t aL = sBuf + ST_AL + aOff;
        const uint32_t bH = sBuf + ST_BH + bOff;
        const uint32_t bL = sBuf + ST_BL + bOff;
        #pragma unroll
        for (int k16 = 0; k16 < 2; k16++){
            const uint32_t ko = (uint32_t)k16 * 32;
            uint32_t A_[16], A2_[16], B_[16];
            #pragma unroll
            for (int mi = 0; mi < 4; mi++)
                ldsm4(A_[4*mi], A_[4*mi+1], A_[4*mi+2], A_[4*mi+3],
                      aH + ko + (uint32_t)mi * (16*ROWB));
            #pragma unroll
            for (int mi = 0; mi < 4; mi++)
                ldsm4(A2_[4*mi], A2_[4*mi+1], A2_[4*mi+2], A2_[4*mi+3],
                      aL + ko + (uint32_t)mi * (16*ROWB));
            #pragma unroll
            for (int j = 0; j < 4; j++)
                ldsm4(B_[4*j], B_[4*j+1], B_[4*j+2], B_[4*j+3],
                      bH + ko + (uint32_t)j * (16*ROWB));
            #pragma unroll
            for (int mi = 0; mi < 4; mi++)
                #pragma unroll
                for (int ni = 0; ni < 8; ni++)
                    mma_bf16(acc[mi][ni], &A_[4*mi], B_[2*ni], B_[2*ni+1]);
            #pragma unroll
            for (int mi = 0; mi < 4; mi++)
                #pragma unroll
                for (int ni = 0; ni < 8; ni++)
                    mma_bf16(acc[mi][ni], &A2_[4*mi], B_[2*ni], B_[2*ni+1]);
            #pragma unroll
            for (int j = 0; j < 4; j++)
                ldsm4(B_[4*j], B_[4*j+1], B_[4*j+2], B_[4*j+3],
                      bL + ko + (uint32_t)j * (16*ROWB));
            #pragma unroll
            for (int mi = 0; mi < 4; mi++)
                #pragma unroll
                for (int ni = 0; ni < 8; ni++)
                    mma_bf16(acc[mi][ni], &A_[4*mi], B_[2*ni], B_[2*ni+1]);
        }
        if (c < 7) stsAB(sb + (uint32_t)((c + 1) & 1) * STG);
        if (c < 6) { ldgA(c + 2); ldgB(c + 2); }
        __syncthreads();
    }

    const int r0q = lane >> 2;
    const int c0q = (lane & 3) * 2;
    #pragma unroll
    for (int mi = 0; mi < 4; mi++){
        #pragma unroll
        for (int half = 0; half < 2; half++){
            const int row = m0 + mW + mi * 16 + half * 8 + r0q;
            if (QKV){
                const int nb = row / SEQ, l = row % SEQ;
                float* base = dst + (((size_t)nb * NHEAD) * SEQ + l) * DHEAD;
                #pragma unroll
                for (int ni = 0; ni < 8; ni++){
                    const int col = nW + ni * 8 + c0q;
                    const int h = col >> 5, cc = col & 31;
                    float2 v;
                    v.x = acc[mi][ni][half*2+0];
                    v.y = acc[mi][ni][half*2+1];
                    *(float2*)(base + (size_t)h * (SEQ*DHEAD) + cc) = v;
                }
            } else {
                float* base = dst + (size_t)row * DMOD;
                #pragma unroll
                for (int ni = 0; ni < 8; ni++){
                    const int col = nW + ni * 8 + c0q;
                    float2 v;
                    v.x = acc[mi][ni][half*2+0];
                    v.y = acc[mi][ni][half*2+1];
                    *(float2*)(base + col) = v;
                }
            }
        }
    }
}

// ---------------- banded attention (R5-proven): one block per (n,h) --------
__global__ void __launch_bounds__(96) attn_kernel(const float* __restrict__ rel_bias)
{
    const int nh = blockIdx.x;
    const int h  = nh & 7;
    const int n  = nh >> 3;

    __shared__ __align__(16) float ks[SEQ][34];
    __shared__ __align__(16) float vs[SEQ][34];
    __shared__ float sbias[NDIAG];

    const int tid = threadIdx.x;
    const float* kg = g_k + (size_t)nh * (SEQ * DHEAD);
    const float* vg = g_v + (size_t)nh * (SEQ * DHEAD);

    for (int idx = tid; idx < SEQ * DHEAD; idx += 96) {
        const int r = idx >> 5, c = idx & 31;
        ks[r][c] = kg[idx];
        vs[r][c] = vg[idx];
    }
    if (tid < NDIAG) {
        const int dd  = tid - 16;
        const int rel = (96 - dd) % 96;
        sbias[tid] = rel_bias[h * 96 + rel];
    }
    __syncthreads();

    const int i = tid;
    const float* qg = g_q + (size_t)nh * (SEQ * DHEAD) + (size_t)i * DHEAD;
    float qv[32];
    #pragma unroll
    for (int c4 = 0; c4 < 8; c4++) {
        float4 t = *(const float4*)(qg + c4 * 4);
        qv[c4*4+0] = t.x; qv[c4*4+1] = t.y; qv[c4*4+2] = t.z; qv[c4*4+3] = t.w;
    }
    ull qq[16];
    #pragma unroll
    for (int t = 0; t < 16; t++) qq[t] = pack2(qv[2*t], qv[2*t+1]);

    const float scale = 0.17677669529663687f;
    float logit[NDIAG];
    #pragma unroll
    for (int d = 0; d < NDIAG; d++) {
        int j = i + d - 16;
        if (j < 0)   j += 96;
        if (j >= 96) j -= 96;
        const ull* kp = (const ull*)&ks[j][0];
        ull a2 = 0ull;
        #pragma unroll
        for (int t = 0; t < 16; t++) ffma2(a2, qq[t], kp[t]);
        float2 s2 = unpack2(a2);
        logit[d] = (s2.x + s2.y) * scale + sbias[d];
    }

    float mx = logit[0];
    #pragma unroll
    for (int d = 1; d < NDIAG; d++) mx = fmaxf(mx, logit[d]);
    float sum = 0.f;
    #pragma unroll
    for (int d = 0; d < NDIAG; d++) { logit[d] = __expf(logit[d] - mx); sum += logit[d]; }

    ull o2[16];
    #pragma unroll
    for (int t = 0; t < 16; t++) o2[t] = 0ull;
    #pragma unroll
    for (int d = 0; d < NDIAG; d++) {
        int j = i + d - 16;
        if (j < 0)   j += 96;
        if (j >= 96) j -= 96;
        const ull ww = pack2(logit[d], logit[d]);
        const ull* vp = (const ull*)&vs[j][0];
        #pragma unroll
        for (int t = 0; t < 16; t++) ffma2(o2[t], ww, vp[t]);
    }

    const float inv = 1.0f / sum;
    float* og = g_ao + ((size_t)n * SEQ + i) * DMOD + h * DHEAD;
    #pragma unroll
    for (int t = 0; t < 16; t++) {
        float2 v = unpack2(o2[t]);
        float2 r; r.x = v.x * inv; r.y = v.y * inv;
        *(float2*)(og + 2 * t) = r;
    }
}

// ---------------- entry point ----------------
extern "C" void kernel_launch(void* const* d_in, const int* in_sizes, int n_in,
                              void* d_out, int out_size)
{
    (void)in_sizes; (void)n_in; (void)out_size;
    const float* Z  = (const float*)d_in[0];
    const float* Wq = (const float*)d_in[1];
    const float* Wk = (const float*)d_in[2];
    const float* Wv = (const float*)d_in[3];
    const float* Wo = (const float*)d_in[4];
    const float* rb = (const float*)d_in[5];
    float* out = (float*)d_out;

    cudaFuncSetAttribute(gemm_mma<1>, cudaFuncAttributeMaxDynamicSharedMemorySize, SMEMB);
    cudaFuncSetAttribute(gemm_mma<0>, cudaFuncAttributeMaxDynamicSharedMemorySize, SMEMB);

    // z fastest: the 3 QKV CTAs of each m-tile run concurrently and share A in L2
    dim3 g1(3, MTOT / 128);
    gemm_mma<1><<<g1, 256, SMEMB>>>(Z, Wq, Wk, Wv, nullptr);

    attn_kernel<<<NBATCH * NHEAD, 96>>>(rb);

    dim3 g2(MTOT / 128, 1);
    gemm_mma<0><<<g2, 256, SMEMB>>>(nullptr, Wo, nullptr, nullptr, out);
}

// round 17
// speedup vs baseline: 1.6880x; 1.0822x over previous
#include <cuda_runtime.h>
#include <cstdint>

typedef unsigned long long ull;

#define SEQ    96
#define NHEAD  8
#define DHEAD  32
#define DMOD   256
#define NBATCH 1024
#define MTOT   (NBATCH*SEQ)   // 98304
#define NDIAG  33

// ---------------- scratch (static device globals) ----------------
__device__ float g_q[NBATCH*NHEAD*SEQ*DHEAD];
__device__ float g_k[NBATCH*NHEAD*SEQ*DHEAD];
__device__ float g_v[NBATCH*NHEAD*SEQ*DHEAD];
__device__ float g_ao[MTOT*DMOD];

// ---------------- helpers ----------------
__device__ __forceinline__ ull pack2(float x, float y) {
    ull r; asm("mov.b64 %0, {%1,%2};" : "=l"(r) : "f"(x), "f"(y)); return r;
}
__device__ __forceinline__ void ffma2(ull &d, ull a, ull b) {
    asm("fma.rn.f32x2 %0, %1, %2, %0;" : "+l"(d) : "l"(a), "l"(b));
}
__device__ __forceinline__ float2 unpack2(ull v) {
    float2 f; asm("mov.b64 {%0,%1}, %2;" : "=f"(f.x), "=f"(f.y) : "l"(v)); return f;
}
__device__ __forceinline__ uint32_t smem_u32(const void* p){
    uint32_t a;
    asm("{ .reg .u64 t; cvta.to.shared.u64 t, %1; cvt.u32.u64 %0, t; }" : "=r"(a) : "l"(p));
    return a;
}
__device__ __forceinline__ void ldsm4(uint32_t& r0, uint32_t& r1, uint32_t& r2,
                                      uint32_t& r3, uint32_t a){
    asm volatile("ldmatrix.sync.aligned.m8n8.x4.shared.b16 {%0,%1,%2,%3}, [%4];"
        : "=r"(r0), "=r"(r1), "=r"(r2), "=r"(r3) : "r"(a));
}
__device__ __forceinline__ void mma_bf16(float* c, const uint32_t* a,
                                         uint32_t b0, uint32_t b1){
    asm volatile("mma.sync.aligned.m16n8k16.row.col.f32.bf16.bf16.f32 "
        "{%0,%1,%2,%3}, {%4,%5,%6,%7}, {%8,%9}, {%0,%1,%2,%3};"
        : "+f"(c[0]), "+f"(c[1]), "+f"(c[2]), "+f"(c[3])
        : "r"(a[0]), "r"(a[1]), "r"(a[2]), "r"(a[3]), "r"(b0), "r"(b1));
}
__device__ __forceinline__ void bsplit2(float x, float y, uint32_t& h2, uint32_t& l2){
    asm("cvt.rn.bf16x2.f32 %0, %1, %2;" : "=r"(h2) : "f"(y), "f"(x));
    float hx = __uint_as_float(h2 << 16);
    float hy = __uint_as_float(h2 & 0xffff0000u);
    float rx = x - hx;
    float ry = y - hy;
    asm("cvt.rn.bf16x2.f32 %0, %1, %2;" : "=r"(l2) : "f"(ry), "f"(rx));
}
__device__ __forceinline__ void sts128(uint32_t a, uint32_t r0, uint32_t r1,
                                       uint32_t r2, uint32_t r3){
    asm volatile("st.shared.v4.b32 [%0], {%1,%2,%3,%4};"
        :: "r"(a), "r"(r0), "r"(r1), "r"(r2), "r"(r3) : "memory");
}
__device__ __forceinline__ void sts16(uint32_t a, uint32_t v){
    asm volatile("st.shared.u16 [%0], %1;" :: "r"(a), "r"(v) : "memory");
}

// SMEM stage layout (bf16 tiles, rows padded to 80B)
#define ROWB  80
#define ST_AH 0
#define ST_AL 10240
#define ST_BH 20480
#define ST_BL 40960
#define STG   61440
#define SMEMB (2*STG)   // 122880

// ---------------- bf16x3 tensor-core GEMM (R16-banked: 357/118us) ----------
template<int QKV>
__global__ void __launch_bounds__(256, 1) gemm_mma(
    const float* __restrict__ Ain,
    const float* __restrict__ W0, const float* __restrict__ W1,
    const float* __restrict__ W2,
    float* __restrict__ Cout)
{
    extern __shared__ __align__(128) char smem[];
    const uint32_t sb = smem_u32(smem);
    const int tid  = threadIdx.x;
    const int lane = tid & 31;
    const int wid  = tid >> 5;

    const float* W; float* dst;
    if (QKV) {
        const int z = blockIdx.x;
        W   = (z == 0) ? W0  : (z == 1) ? W1  : W2;
        dst = (z == 0) ? g_q : (z == 1) ? g_k : g_v;
    } else { W = W0; dst = Cout; }
    const float* Ab = QKV ? Ain : (const float*)g_ao;
    const int m0 = (QKV ? blockIdx.y : blockIdx.x) * 128;

    const int ar = tid & 127;
    const int ah = (tid >> 7) << 4;
    const float* gA = Ab + (size_t)(m0 + ar) * DMOD + ah;
    const uint32_t aDst = (uint32_t)ar * ROWB + (uint32_t)(ah << 1);
    const float* gB = W + tid;
    const uint32_t bDst = (uint32_t)tid * ROWB;

    const int mW = (wid & 1) * 64;
    const int nW = (wid >> 1) * 64;
    const int q  = lane >> 3;
    const int rl = lane & 7;
    const uint32_t aOff = (uint32_t)(mW + (q & 1) * 8 + rl) * ROWB + (uint32_t)((q >> 1) * 16);
    const uint32_t bOff = (uint32_t)(nW + (q >> 1) * 8 + rl) * ROWB + (uint32_t)((q & 1) * 16);

    float acc[4][8][4];
    #pragma unroll
    for (int mi = 0; mi < 4; mi++)
        #pragma unroll
        for (int ni = 0; ni < 8; ni++)
            #pragma unroll
            for (int t = 0; t < 4; t++) acc[mi][ni][t] = 0.f;

    float fa[16], fb[32];

    auto ldgA = [&](int c){
        const float* p = gA + c * 32;
        *(float4*)(fa + 0)  = *(const float4*)(p + 0);
        *(float4*)(fa + 4)  = *(const float4*)(p + 4);
        *(float4*)(fa + 8)  = *(const float4*)(p + 8);
        *(float4*)(fa + 12) = *(const float4*)(p + 12);
    };
    auto ldgB = [&](int c){
        const float* p = gB + (size_t)c * 32 * DMOD;
        #pragma unroll
        for (int i = 0; i < 32; i++) fb[i] = p[(size_t)i * DMOD];
    };
    auto stsAB = [&](uint32_t sBase){
        uint32_t h[16], l[16];
        #pragma unroll
        for (int i = 0; i < 8; i++) bsplit2(fa[2*i], fa[2*i+1], h[i], l[i]);
        sts128(sBase + ST_AH + aDst,      h[0], h[1], h[2], h[3]);
        sts128(sBase + ST_AH + aDst + 16, h[4], h[5], h[6], h[7]);
        sts128(sBase + ST_AL + aDst,      l[0], l[1], l[2], l[3]);
        sts128(sBase + ST_AL + aDst + 16, l[4], l[5], l[6], l[7]);
        #pragma unroll
        for (int i = 0; i < 16; i++) bsplit2(fb[2*i], fb[2*i+1], h[i], l[i]);
        sts128(sBase + ST_BH + bDst,      h[0],  h[1],  h[2],  h[3]);
        sts128(sBase + ST_BH + bDst + 16, h[4],  h[5],  h[6],  h[7]);
        sts128(sBase + ST_BH + bDst + 32, h[8],  h[9],  h[10], h[11]);
        sts128(sBase + ST_BH + bDst + 48, h[12], h[13], h[14], h[15]);
        sts128(sBase + ST_BL + bDst,      l[0],  l[1],  l[2],  l[3]);
        sts128(sBase + ST_BL + bDst + 16, l[4],  l[5],  l[6],  l[7]);
        sts128(sBase + ST_BL + bDst + 32, l[8],  l[9],  l[10], l[11]);
        sts128(sBase + ST_BL + bDst + 48, l[12], l[13], l[14], l[15]);
    };

    ldgA(0); ldgB(0);
    stsAB(sb);
    ldgA(1); ldgB(1);
    __syncthreads();

    #pragma unroll 1
    for (int c = 0; c < 8; c++){
        const uint32_t sBuf = sb + (uint32_t)(c & 1) * STG;
        const uint32_t aH = sBuf + ST_AH + aOff;
        const uint32_t aL = sBuf + ST_AL + aOff;
        const uint32_t bH = sBuf + ST_BH + bOff;
        const uint32_t bL = sBuf + ST_BL + bOff;
        #pragma unroll
        for (int k16 = 0; k16 < 2; k16++){
            const uint32_t ko = (uint32_t)k16 * 32;
            uint32_t A_[16], A2_[16], B_[16];
            #pragma unroll
            for (int mi = 0; mi < 4; mi++)
                ldsm4(A_[4*mi], A_[4*mi+1], A_[4*mi+2], A_[4*mi+3],
                      aH + ko + (uint32_t)mi * (16*ROWB));
            #pragma unroll
            for (int mi = 0; mi < 4; mi++)
                ldsm4(A2_[4*mi], A2_[4*mi+1], A2_[4*mi+2], A2_[4*mi+3],
                      aL + ko + (uint32_t)mi * (16*ROWB));
            #pragma unroll
            for (int j = 0; j < 4; j++)
                ldsm4(B_[4*j], B_[4*j+1], B_[4*j+2], B_[4*j+3],
                      bH + ko + (uint32_t)j * (16*ROWB));
            #pragma unroll
            for (int mi = 0; mi < 4; mi++)
                #pragma unroll
                for (int ni = 0; ni < 8; ni++)
                    mma_bf16(acc[mi][ni], &A_[4*mi], B_[2*ni], B_[2*ni+1]);
            #pragma unroll
            for (int mi = 0; mi < 4; mi++)
                #pragma unroll
                for (int ni = 0; ni < 8; ni++)
                    mma_bf16(acc[mi][ni], &A2_[4*mi], B_[2*ni], B_[2*ni+1]);
            #pragma unroll
            for (int j = 0; j < 4; j++)
                ldsm4(B_[4*j], B_[4*j+1], B_[4*j+2], B_[4*j+3],
                      bL + ko + (uint32_t)j * (16*ROWB));
            #pragma unroll
            for (int mi = 0; mi < 4; mi++)
                #pragma unroll
                for (int ni = 0; ni < 8; ni++)
                    mma_bf16(acc[mi][ni], &A_[4*mi], B_[2*ni], B_[2*ni+1]);
        }
        if (c < 7) stsAB(sb + (uint32_t)((c + 1) & 1) * STG);
        if (c < 6) { ldgA(c + 2); ldgB(c + 2); }
        __syncthreads();
    }

    const int r0q = lane >> 2;
    const int c0q = (lane & 3) * 2;
    #pragma unroll
    for (int mi = 0; mi < 4; mi++){
        #pragma unroll
        for (int half = 0; half < 2; half++){
            const int row = m0 + mW + mi * 16 + half * 8 + r0q;
            if (QKV){
                const int nb = row / SEQ, l = row % SEQ;
                float* base = dst + (((size_t)nb * NHEAD) * SEQ + l) * DHEAD;
                #pragma unroll
                for (int ni = 0; ni < 8; ni++){
                    const int col = nW + ni * 8 + c0q;
                    const int h = col >> 5, cc = col & 31;
                    float2 v;
                    v.x = acc[mi][ni][half*2+0];
                    v.y = acc[mi][ni][half*2+1];
                    *(float2*)(base + (size_t)h * (SEQ*DHEAD) + cc) = v;
                }
            } else {
                float* base = dst + (size_t)row * DMOD;
                #pragma unroll
                for (int ni = 0; ni < 8; ni++){
                    const int col = nW + ni * 8 + c0q;
                    float2 v;
                    v.x = acc[mi][ni][half*2+0];
                    v.y = acc[mi][ni][half*2+1];
                    *(float2*)(base + col) = v;
                }
            }
        }
    }
}

// ---------------- tensor-core attention: one block (96 thr) per (n,h) ------
// QK = Q.K^T (bf16x3), max-free softmax in fragments, PV with weights
// converted f32->bf16 hi/lo IN REGISTERS (C-frag == A-frag layout).
#define SQH 0
#define SQL 7680
#define SKH 15360
#define SKL 23040
#define ROWV 208
#define SVH 30720
#define SVL 37376
#define SBIA 44032
#define ASMEM 44176

__global__ void __launch_bounds__(96) attn_mma(const float* __restrict__ rel_bias)
{
    __shared__ __align__(128) char sm[ASMEM];
    const uint32_t sb = smem_u32(sm);
    const int tid = threadIdx.x;
    const int nh  = blockIdx.x;
    const int h   = nh & 7;
    const int nb  = nh >> 3;

    // ---- load Q,K rows (split, 80B rows) ----
    {
        const float* qg = g_q + (size_t)nh * 3072 + (size_t)tid * 32;
        const float* kg = g_k + (size_t)nh * 3072 + (size_t)tid * 32;
        float r[32];
        uint32_t hh[16], ll[16];
        #pragma unroll
        for (int i = 0; i < 8; i++) *(float4*)(r + 4*i) = *(const float4*)(qg + 4*i);
        #pragma unroll
        for (int i = 0; i < 16; i++) bsplit2(r[2*i], r[2*i+1], hh[i], ll[i]);
        #pragma unroll
        for (int s = 0; s < 4; s++){
            sts128(sb + SQH + tid*ROWB + 16*s, hh[4*s], hh[4*s+1], hh[4*s+2], hh[4*s+3]);
            sts128(sb + SQL + tid*ROWB + 16*s, ll[4*s], ll[4*s+1], ll[4*s+2], ll[4*s+3]);
        }
        #pragma unroll
        for (int i = 0; i < 8; i++) *(float4*)(r + 4*i) = *(const float4*)(kg + 4*i);
        #pragma unroll
        for (int i = 0; i < 16; i++) bsplit2(r[2*i], r[2*i+1], hh[i], ll[i]);
        #pragma unroll
        for (int s = 0; s < 4; s++){
            sts128(sb + SKH + tid*ROWB + 16*s, hh[4*s], hh[4*s+1], hh[4*s+2], hh[4*s+3]);
            sts128(sb + SKL + tid*ROWB + 16*s, ll[4*s], ll[4*s+1], ll[4*s+2], ll[4*s+3]);
        }
        // V transposed: Vt[dim][key], single bf16 stores
        const float* vg = g_v + (size_t)nh * 3072 + (size_t)tid * 32;
        #pragma unroll
        for (int i = 0; i < 8; i++) *(float4*)(r + 4*i) = *(const float4*)(vg + 4*i);
        #pragma unroll
        for (int d = 0; d < 32; d++){
            uint32_t h2, l2;
            bsplit2(r[d], 0.f, h2, l2);
            sts16(sb + SVH + d*ROWV + tid*2, h2 & 0xffffu);
            sts16(sb + SVL + d*ROWV + tid*2, l2 & 0xffffu);
        }
    }
    if (tid < NDIAG){
        const int rel = (112 - tid) % 96;   // (i-j) mod 96 for offset j-i = tid-16
        *(float*)(sm + SBIA + 4*tid) = rel_bias[h * 96 + rel];
    }
    __syncthreads();

    const int w    = tid >> 5;
    const int lane = tid & 31;
    const int q    = lane >> 3;
    const int rl   = lane & 7;
    const int gID  = lane >> 2;
    const int tg   = lane & 3;
    const float* sbias = (const float*)(sm + SBIA);
    const float scale = 0.17677669529663687f;   // 1/sqrt(32)

    // ---- QK: L[mt][nt][4], mt = warp m-tile (rows w*32+16mt..+15) ----
    float L[2][12][4];
    #pragma unroll
    for (int mt = 0; mt < 2; mt++)
        #pragma unroll
        for (int nt = 0; nt < 12; nt++)
            #pragma unroll
            for (int c = 0; c < 4; c++) L[mt][nt][c] = 0.f;

    const uint32_t aRow = (uint32_t)((q & 1) * 8 + rl) * ROWB + (uint32_t)((q >> 1) * 16);
    const uint32_t bRow = (uint32_t)((q >> 1) * 8 + rl) * ROWB + (uint32_t)((q & 1) * 16);

    #pragma unroll
    for (int ks = 0; ks < 2; ks++){
        const uint32_t ko = (uint32_t)ks * 32;
        uint32_t KH[24], KL[24];
        #pragma unroll
        for (int kb = 0; kb < 6; kb++){
            ldsm4(KH[4*kb], KH[4*kb+1], KH[4*kb+2], KH[4*kb+3],
                  sb + SKH + (uint32_t)kb * (16*ROWB) + bRow + ko);
            ldsm4(KL[4*kb], KL[4*kb+1], KL[4*kb+2], KL[4*kb+3],
                  sb + SKL + (uint32_t)kb * (16*ROWB) + bRow + ko);
        }
        #pragma unroll
        for (int mt = 0; mt < 2; mt++){
            const uint32_t mrow = (uint32_t)(w * 32 + mt * 16) * ROWB;
            uint32_t QH[4], QL[4];
            ldsm4(QH[0], QH[1], QH[2], QH[3], sb + SQH + mrow + aRow + ko);
            ldsm4(QL[0], QL[1], QL[2], QL[3], sb + SQL + mrow + aRow + ko);
            #pragma unroll
            for (int nt = 0; nt < 12; nt++){
                const int kb = nt >> 1, p = (nt & 1) * 2;
                mma_bf16(L[mt][nt], QH, KH[4*kb + p], KH[4*kb + p + 1]);
                mma_bf16(L[mt][nt], QH, KL[4*kb + p], KL[4*kb + p + 1]);
                mma_bf16(L[mt][nt], QL, KH[4*kb + p], KH[4*kb + p + 1]);
            }
        }
    }

    // ---- mask + bias + exp (max-free), row sums, pack weights to bf16 hi/lo
    float rsum[2][2] = {{0.f, 0.f}, {0.f, 0.f}};
    #pragma unroll
    for (int mt = 0; mt < 2; mt++)
        #pragma unroll
        for (int nt = 0; nt < 12; nt++)
            #pragma unroll
            for (int c = 0; c < 4; c++){
                const int i = w * 32 + mt * 16 + ((c >> 1) ? 8 : 0) + gID;
                const int j = nt * 8 + 2 * tg + (c & 1);
                int dd = j - i;
                if (dd >  48) dd -= 96;
                if (dd < -48) dd += 96;
                const bool valid = (dd >= -16) && (dd <= 16);
                float wv = 0.f;
                if (valid)
                    wv = __expf(L[mt][nt][c] * scale + sbias[dd + 16]);
                L[mt][nt][c] = wv;
                rsum[mt][c >> 1] += wv;
            }
    #pragma unroll
    for (int mt = 0; mt < 2; mt++)
        #pragma unroll
        for (int hf = 0; hf < 2; hf++){
            float s = rsum[mt][hf];
            s += __shfl_xor_sync(0xffffffffu, s, 1);
            s += __shfl_xor_sync(0xffffffffu, s, 2);
            rsum[mt][hf] = 1.0f / s;
        }

    uint32_t WH[2][6][4], WL[2][6][4];
    #pragma unroll
    for (int mt = 0; mt < 2; mt++)
        #pragma unroll
        for (int kt = 0; kt < 6; kt++){
            bsplit2(L[mt][2*kt][0],   L[mt][2*kt][1],   WH[mt][kt][0], WL[mt][kt][0]);
            bsplit2(L[mt][2*kt][2],   L[mt][2*kt][3],   WH[mt][kt][1], WL[mt][kt][1]);
            bsplit2(L[mt][2*kt+1][0], L[mt][2*kt+1][1], WH[mt][kt][2], WL[mt][kt][2]);
            bsplit2(L[mt][2*kt+1][2], L[mt][2*kt+1][3], WH[mt][kt][3], WL[mt][kt][3]);
        }

    // ---- PV: O[mt][nt][4] over V^T (dims as n, keys as k) ----
    float O[2][4][4];
    #pragma unroll
    for (int mt = 0; mt < 2; mt++)
        #pragma unroll
        for (int nt = 0; nt < 4; nt++)
            #pragma unroll
            for (int c = 0; c < 4; c++) O[mt][nt][c] = 0.f;

    const uint32_t vRow = (uint32_t)((q >> 1) * 8 + rl) * ROWV + (uint32_t)((q & 1) * 16);
    #pragma unroll
    for (int kt = 0; kt < 6; kt++){
        const uint32_t ko = (uint32_t)kt * 32;
        uint32_t VH[8], VL[8];
        ldsm4(VH[0], VH[1], VH[2], VH[3], sb + SVH + vRow + ko);
        ldsm4(VH[4], VH[5], VH[6], VH[7], sb + SVH + 16*ROWV + vRow + ko);
        ldsm4(VL[0], VL[1], VL[2], VL[3], sb + SVL + vRow + ko);
        ldsm4(VL[4], VL[5], VL[6], VL[7], sb + SVL + 16*ROWV + vRow + ko);
        #pragma unroll
        for (int mt = 0; mt < 2; mt++)
            #pragma unroll
            for (int nt = 0; nt < 4; nt++){
                mma_bf16(O[mt][nt], WH[mt][kt], VH[2*nt], VH[2*nt+1]);
                mma_bf16(O[mt][nt], WH[mt][kt], VL[2*nt], VL[2*nt+1]);
                mma_bf16(O[mt][nt], WL[mt][kt], VH[2*nt], VH[2*nt+1]);
            }
    }

    // ---- epilogue: divide by row sum, write [n*96+i][h*32+col] ----
    #pragma unroll
    for (int mt = 0; mt < 2; mt++)
        #pragma unroll
        for (int hf = 0; hf < 2; hf++){
            const int i = w * 32 + mt * 16 + hf * 8 + gID;
            const float inv = rsum[mt][hf];
            float* base = g_ao + ((size_t)nb * SEQ + i) * DMOD + h * DHEAD;
            #pragma unroll
            for (int nt = 0; nt < 4; nt++){
                float2 v;
                v.x = O[mt][nt][hf*2+0] * inv;
                v.y = O[mt][nt][hf*2+1] * inv;
                *(float2*)(base + nt * 8 + 2 * tg) = v;
            }
        }
}

// ---------------- entry point ----------------
extern "C" void kernel_launch(void* const* d_in, const int* in_sizes, int n_in,
                              void* d_out, int out_size)
{
    (void)in_sizes; (void)n_in; (void)out_size;
    const float* Z  = (const float*)d_in[0];
    const float* Wq = (const float*)d_in[1];
    const float* Wk = (const float*)d_in[2];
    const float* Wv = (const float*)d_in[3];
    const float* Wo = (const float*)d_in[4];
    const float* rb = (const float*)d_in[5];
    float* out = (float*)d_out;

    cudaFuncSetAttribute(gemm_mma<1>, cudaFuncAttributeMaxDynamicSharedMemorySize, SMEMB);
    cudaFuncSetAttribute(gemm_mma<0>, cudaFuncAttributeMaxDynamicSharedMemorySize, SMEMB);

    dim3 g1(3, MTOT / 128);
    gemm_mma<1><<<g1, 256, SMEMB>>>(Z, Wq, Wk, Wv, nullptr);

    attn_mma<<<NBATCH * NHEAD, 96>>>(rb);

    dim3 g2(MTOT / 128, 1);
    gemm_mma<0><<<g2, 256, SMEMB>>>(nullptr, Wo, nullptr, nullptr, out);
}